// round 16
// baseline (speedup 1.0000x reference)
#include <cuda_runtime.h>
#include <cuda_fp16.h>
#include <math.h>
#include <stdint.h>

#define B_  4
#define S_  8192
#define D_  1024
#define H_  16
#define M_  (B_*S_)

// ---------------- scratch (device globals; no cudaMalloc) ----------------
__device__ __half g_Ah[(size_t)M_ * D_];                // fp16(hs)
__device__ __half g_mqh[(size_t)M_ * D_];               // fp16 mixed_q
__device__ __half g_mkh[(size_t)M_ * D_];               // fp16 mixed_k
__device__ __half g_Bqk[2048 * 1024];                   // [n,k] fp16 (Wq cols | Wk cols)
__device__ float  g_Wtt[1024 * 1024];                   // Wt^T fp32 [n,k]
__device__ __half g_Bt4[4 * 1024 * 1024];               // per-batch fp16(Wt^T * pk)
__device__ float g_score[B_ * H_ * S_];
__device__ float g_part[512 * 65];
__device__ float g_pq[B_ * D_];
__device__ float g_pk[B_ * D_];

// ---------------- helpers (sm_80-era PTX only: portable to sm_103) ----------------
__device__ __forceinline__ uint32_t smem_u32(const void* p) {
    uint32_t a;
    asm("{ .reg .u64 t; cvta.to.shared.u64 t, %1; cvt.u32.u64 %0, t; }" : "=r"(a) : "l"(p));
    return a;
}
__device__ __forceinline__ void cp16(uint32_t dst, const void* src) {
    asm volatile("cp.async.cg.shared.global [%0], [%1], 16;" :: "r"(dst), "l"(src));
}
__device__ __forceinline__ void ldsm4(uint32_t* r, uint32_t addr) {
    asm volatile("ldmatrix.sync.aligned.m8n8.x4.shared.b16 {%0,%1,%2,%3}, [%4];"
                 : "=r"(r[0]), "=r"(r[1]), "=r"(r[2]), "=r"(r[3]) : "r"(addr));
}
__device__ __forceinline__ void mma16816(float* d, const uint32_t* a, const uint32_t* b) {
    asm volatile("mma.sync.aligned.m16n8k16.row.col.f32.f16.f16.f32 "
                 "{%0,%1,%2,%3}, {%4,%5,%6,%7}, {%8,%9}, {%0,%1,%2,%3};"
                 : "+f"(d[0]), "+f"(d[1]), "+f"(d[2]), "+f"(d[3])
                 : "r"(a[0]), "r"(a[1]), "r"(a[2]), "r"(a[3]), "r"(b[0]), "r"(b[1]));
}

// =====================================================================
// Weight prep, single launch: z=0 Wq->bqk, z=1 Wk->bqk+1M (fp16),
// z=2 Wt->wtt (fp32). All transpose [k][n] -> [n][k].
// =====================================================================
__global__ void wprep_all_kernel(const float* __restrict__ Wq, const float* __restrict__ Wk,
                                 const float* __restrict__ Wt,
                                 __half* __restrict__ bqk, float* __restrict__ wtt)
{
    __shared__ float t[32][33];
    const float* W = (blockIdx.z == 0) ? Wq : (blockIdx.z == 1) ? Wk : Wt;
    int n0 = blockIdx.x * 32, k0 = blockIdx.y * 32;
    int tx = threadIdx.x, ty = threadIdx.y;
    for (int i = ty; i < 32; i += 8)
        t[i][tx] = W[(size_t)(k0 + i) * 1024 + n0 + tx];
    __syncthreads();
    if (blockIdx.z < 2) {
        __half* o = bqk + (size_t)blockIdx.z * 1024 * 1024;
        for (int i = ty; i < 32; i += 8)
            o[(size_t)(n0 + i) * 1024 + k0 + tx] = __float2half(t[tx][i]);
    } else {
        for (int i = ty; i < 32; i += 8)
            wtt[(size_t)(n0 + i) * 1024 + k0 + tx] = t[tx][i];
    }
}

// B4[b][n][k] = fp16(Wtt[n][k] * pk[b][k])   (single rounding of the product)
__global__ __launch_bounds__(256)
void wtscale_kernel(const float* __restrict__ Wtt, const float* __restrict__ pk,
                    __half* __restrict__ B4)
{
    int i = blockIdx.x * 256 + threadIdx.x;   // float4 index into [n][k]
    int k4 = (i << 2) & 1023;
    float4 w = ((const float4*)Wtt)[i];
    #pragma unroll
    for (int b = 0; b < 4; b++) {
        float4 s = *(const float4*)&pk[b * 1024 + k4];
        __half2 h0 = __floats2half2_rn(w.x * s.x, w.y * s.y);
        __half2 h1 = __floats2half2_rn(w.z * s.z, w.w * s.w);
        ((uint2*)(B4 + ((size_t)b << 20)))[i] =
            make_uint2(*(uint32_t*)&h0, *(uint32_t*)&h1);
    }
}

// =====================================================================
// A convert: fp16 of hs (2 float4 per thread)
// =====================================================================
__global__ __launch_bounds__(256)
void asplit_kernel(const float* __restrict__ X, __half* __restrict__ hi)
{
    size_t i = ((size_t)blockIdx.x * 256 + threadIdx.x) * 2;   // float4 index
    #pragma unroll
    for (int j = 0; j < 2; j++) {
        float4 v = ((const float4*)X)[i + j];
        __half2 h0 = __floats2half2_rn(v.x, v.y);
        __half2 h1 = __floats2half2_rn(v.z, v.w);
        ((uint2*)hi)[i + j] = make_uint2(*(uint32_t*)&h0, *(uint32_t*)&h1);
    }
}

// =====================================================================
// HMMA fp16 1-pass GEMM. CTA 128x256, 8 warps, warp tile 64x64, BK=32,
// 4-stage cp.async.  G3=false: dual fp16 outputs (mq|mk) + fp32 bias.
// G3=true: per-batch B (Bt4), fp32 output, fp16 residual addC.
// =====================================================================
#define STAGE_BYTES 30720u
#define NSTAGE 4

__device__ __forceinline__ void issue_stage(
    int s, uint32_t smb, int brow, int bcol,
    const __half* Ab, const __half* Bb, int rr, int cc)
{
    const int st = s & (NSTAGE - 1);
    const int k0 = s << 5;
    uint32_t As = smb + (uint32_t)st * STAGE_BYTES;
    uint32_t Bs = As + 10240u;
    #pragma unroll
    for (int i = 0; i < 2; i++) {
        int r = rr + i * 64;
        cp16(As + (uint32_t)(r * 80 + cc * 2), Ab + (size_t)(brow + r) * 1024 + k0 + cc);
    }
    #pragma unroll
    for (int i = 0; i < 4; i++) {
        int r = rr + i * 64;
        cp16(Bs + (uint32_t)(r * 80 + cc * 2), Bb + (size_t)(bcol + r) * 1024 + k0 + cc);
    }
    asm volatile("cp.async.commit_group;" ::: "memory");
}

template<bool G3>
__global__ __launch_bounds__(256, 1)
void hmma_gemm_kernel(const __half* __restrict__ Ah, const __half* __restrict__ B,
                      const float* __restrict__ bias0, const float* __restrict__ bias1,
                      const __half* __restrict__ addCh,
                      void* __restrict__ C0v, void* __restrict__ C1v)
{
    extern __shared__ char smraw[];
    const uint32_t smb = smem_u32(smraw);
    const int tid = threadIdx.x, lane = tid & 31, wid = tid >> 5;
    const int wr = wid & 1, wc = wid >> 1;
    const int brow = blockIdx.y * 128, bcol = blockIdx.x * 256;

    const __half* Bb = B;
    if (G3) Bb += ((size_t)(brow >> 13)) << 20;   // per-batch scaled Wt

    float acc[4][8][4];
    #pragma unroll
    for (int mt = 0; mt < 4; mt++)
        #pragma unroll
        for (int nt = 0; nt < 8; nt++)
            #pragma unroll
            for (int j = 0; j < 4; j++) acc[mt][nt][j] = 0.f;

    const int rr = tid >> 2;
    const int cc = (tid & 3) * 8;

    issue_stage(0, smb, brow, bcol, Ah, Bb, rr, cc);
    issue_stage(1, smb, brow, bcol, Ah, Bb, rr, cc);
    issue_stage(2, smb, brow, bcol, Ah, Bb, rr, cc);

    const int am  = wr * 64 + (lane & 15);
    const int akh = (lane >> 4) * 8;
    const int g   = lane >> 3;
    const int bn  = wc * 64 + (lane & 7) + (g >> 1) * 8;
    const int bkh = (g & 1) * 8;

    for (int s = 0; s < 32; s++) {
        asm volatile("cp.async.wait_group 2;" ::: "memory");
        __syncthreads();
        if (s + 3 < 32) issue_stage(s + 3, smb, brow, bcol, Ah, Bb, rr, cc);
        else            asm volatile("cp.async.commit_group;" ::: "memory");

        uint32_t Asb = smb + (uint32_t)(s & (NSTAGE - 1)) * STAGE_BYTES;
        uint32_t Bsb = Asb + 10240u;
        #pragma unroll
        for (int kk = 0; kk < 2; kk++) {
            const int k = kk * 16;
            uint32_t a[4][4], b[4][4];
            #pragma unroll
            for (int mt = 0; mt < 4; mt++)
                ldsm4(a[mt], Asb + (uint32_t)((am + mt * 16) * 80 + (k + akh) * 2));
            #pragma unroll
            for (int bt = 0; bt < 4; bt++)
                ldsm4(b[bt], Bsb + (uint32_t)((bn + bt * 16) * 80 + (k + bkh) * 2));
            #pragma unroll
            for (int mt = 0; mt < 4; mt++)
                #pragma unroll
                for (int nt = 0; nt < 8; nt++)
                    mma16816(acc[mt][nt], a[mt], &b[nt >> 1][(nt & 1) * 2]);
        }
    }

    if (!G3) {
        // ---- fp16 dual-output epilogue (mixed_q | mixed_k), bias added
        const float* bias = bias0;
        __half* Cd = (__half*)C0v;
        int ceff = bcol;
        if (bcol >= 1024) { bias = bias1; Cd = (__half*)C1v; ceff = bcol - 1024; }
        #pragma unroll
        for (int mt = 0; mt < 4; mt++) {
            const int r = brow + wr * 64 + mt * 16 + (lane >> 2);
            #pragma unroll
            for (int nt = 0; nt < 8; nt++) {
                const int c = ceff + wc * 64 + nt * 8 + (lane & 3) * 2;
                float2 bi = *(const float2*)&bias[c];
                __half2 h0 = __floats2half2_rn(acc[mt][nt][0] + bi.x, acc[mt][nt][1] + bi.y);
                __half2 h1 = __floats2half2_rn(acc[mt][nt][2] + bi.x, acc[mt][nt][3] + bi.y);
                *(uint32_t*)&Cd[(size_t)r * 1024 + c] = *(uint32_t*)&h0;
                *(uint32_t*)&Cd[(size_t)(r + 8) * 1024 + c] = *(uint32_t*)&h1;
            }
        }
    } else {
        // ---- fp32 output epilogue with fp16 residual
        float* Cd = (float*)C0v;
        #pragma unroll
        for (int mt = 0; mt < 4; mt++) {
            const int r = brow + wr * 64 + mt * 16 + (lane >> 2);
            #pragma unroll
            for (int nt = 0; nt < 8; nt++) {
                const int c = bcol + wc * 64 + nt * 8 + (lane & 3) * 2;
                float2 bi = *(const float2*)&bias0[c];
                uint32_t a0u = *(const uint32_t*)&addCh[(size_t)r * 1024 + c];
                uint32_t a1u = *(const uint32_t*)&addCh[(size_t)(r + 8) * 1024 + c];
                float2 a0 = __half22float2(*(__half2*)&a0u);
                float2 a1 = __half22float2(*(__half2*)&a1u);
                float2 v0 = make_float2(acc[mt][nt][0] + bi.x + a0.x,
                                        acc[mt][nt][1] + bi.y + a0.y);
                float2 v1 = make_float2(acc[mt][nt][2] + bi.x + a1.x,
                                        acc[mt][nt][3] + bi.y + a1.y);
                *(float2*)&Cd[(size_t)r * 1024 + c] = v0;
                *(float2*)&Cd[(size_t)(r + 8) * 1024 + c] = v1;
            }
        }
    }
}

// =====================================================================
// score[b,h,s] = (X[b,s,:] (* mul[b,:]) . Wa[:,h] + ba[h]) * 0.125 + mask
// X fp16, Wa cached in smem as fp16, half2 accumulation (HFMA2 pipe).
// 1024 thr = 32 rows/block.
// =====================================================================
__global__ __launch_bounds__(1024)
void score_kernel(const __half* __restrict__ X, const float* __restrict__ Wa,
                  const float* __restrict__ ba, const float* __restrict__ mask,
                  const float* __restrict__ mul, float* __restrict__ score)
{
    extern __shared__ __half WaS[];  // [16][1024] transposed, fp16
    for (int idx = threadIdx.x; idx < 16 * 1024; idx += 1024) {
        int d = idx >> 4, h = idx & 15;
        WaS[h * 1024 + d] = __float2half(Wa[idx]);
    }
    __syncthreads();

    int warp = threadIdx.x >> 5, lane = threadIdx.x & 31;
    int m = blockIdx.x * 32 + warp;
    int b = m >> 13, s = m & 8191;
    const __half* xrow = X + (size_t)m * 1024;
    const float* mrow = mul ? (mul + b * 1024) : (const float*)0;

    __half2 acc2[16];
    #pragma unroll
    for (int h = 0; h < 16; h++) acc2[h] = __float2half2_rn(0.f);

    #pragma unroll
    for (int it = 0; it < 8; it++) {
        int d = it * 128 + lane * 4;
        uint2 xu = *(const uint2*)&xrow[d];        // 4 halves
        __half2 x01 = *(__half2*)&xu.x;
        __half2 x23 = *(__half2*)&xu.y;
        if (mrow) {
            float4 mu = *(const float4*)&mrow[d];
            x01 = __hmul2(x01, __floats2half2_rn(mu.x, mu.y));
            x23 = __hmul2(x23, __floats2half2_rn(mu.z, mu.w));
        }
        #pragma unroll
        for (int h = 0; h < 16; h++) {
            uint2 wu = *(const uint2*)&WaS[h * 1024 + d];
            acc2[h] = __hfma2(x01, *(__half2*)&wu.x, acc2[h]);
            acc2[h] = __hfma2(x23, *(__half2*)&wu.y, acc2[h]);
        }
    }
    float acc[16];
    #pragma unroll
    for (int h = 0; h < 16; h++) {
        float2 f = __half22float2(acc2[h]);
        acc[h] = f.x + f.y;
    }
    #pragma unroll
    for (int off = 16; off > 0; off >>= 1)
        #pragma unroll
        for (int h = 0; h < 16; h++)
            acc[h] += __shfl_xor_sync(0xffffffffu, acc[h], off);

    if (lane == 0) {
        float mk = mask[(b << 13) + s];
        #pragma unroll
        for (int h = 0; h < 16; h++)
            score[(size_t)(b * 16 + h) * 8192 + s] = (acc[h] + ba[h]) * 0.125f + mk;
    }
}

// =====================================================================
// Softmax pooling (no max subtraction: |score| < ~1, exp safe). X fp16.
// =====================================================================
__global__ __launch_bounds__(256)
void pool_partial_kernel(const float* __restrict__ score, const __half* __restrict__ X,
                         float* __restrict__ part)
{
    int bh = blockIdx.x, ch = blockIdx.y;
    int b = bh >> 4, h = bh & 15;
    const float* sc = score + ((size_t)bh << 13) + (ch << 10);
    int tid = threadIdx.x;
    float acc[64];
    #pragma unroll
    for (int j = 0; j < 64; j++) acc[j] = 0.f;
    float sumw = 0.f;
    for (int s = tid; s < 1024; s += 256) {
        float w = __expf(sc[s]);
        sumw += w;
        const uint4* xr = (const uint4*)(X + ((size_t)((b << 13) + (ch << 10) + s)) * 1024 + h * 64);
        #pragma unroll
        for (int j = 0; j < 8; j++) {
            uint4 u = xr[j];
            float2 f0 = __half22float2(*(__half2*)&u.x);
            float2 f1 = __half22float2(*(__half2*)&u.y);
            float2 f2 = __half22float2(*(__half2*)&u.z);
            float2 f3 = __half22float2(*(__half2*)&u.w);
            acc[8*j+0] += w*f0.x; acc[8*j+1] += w*f0.y;
            acc[8*j+2] += w*f1.x; acc[8*j+3] += w*f1.y;
            acc[8*j+4] += w*f2.x; acc[8*j+5] += w*f2.y;
            acc[8*j+6] += w*f3.x; acc[8*j+7] += w*f3.y;
        }
    }
    #pragma unroll
    for (int off = 16; off > 0; off >>= 1) {
        sumw += __shfl_xor_sync(0xffffffffu, sumw, off);
        #pragma unroll
        for (int j = 0; j < 64; j++)
            acc[j] += __shfl_xor_sync(0xffffffffu, acc[j], off);
    }
    __shared__ float sacc[8][64];
    __shared__ float ssum[8];
    int warp = tid >> 5, lane = tid & 31;
    if (lane == 0) ssum[warp] = sumw;
    #pragma unroll
    for (int j = 0; j < 64; j++)
        if ((j & 31) == lane) sacc[warp][j] = acc[j];
    __syncthreads();
    if (tid < 64) {
        float tot = 0.f, Z = 0.f;
        #pragma unroll
        for (int w = 0; w < 8; w++) { tot += sacc[w][tid]; Z += ssum[w]; }
        float* p = part + (size_t)(bh * 8 + ch) * 65;
        p[tid] = tot;
        if (tid == 0) p[64] = Z;
    }
}

__global__ void pool_combine_kernel(const float* __restrict__ part, const float* __restrict__ mul,
                                    float* __restrict__ pooled)
{
    int bh = blockIdx.x, tid = threadIdx.x;  // block 64
    int b = bh >> 4, h = bh & 15;
    float tot = 0.f, Z = 0.f;
    #pragma unroll
    for (int ch = 0; ch < 8; ch++) {
        const float* p = part + (size_t)(bh * 8 + ch) * 65;
        tot += p[tid]; Z += p[64];
    }
    float r = tot / Z;
    if (mul) r *= mul[b * 1024 + h * 64 + tid];
    pooled[b * 1024 + h * 64 + tid] = r;
}

// =====================================================================
extern "C" void kernel_launch(void* const* d_in, const int* in_sizes, int n_in,
                              void* d_out, int out_size)
{
    const float* hs   = (const float*)d_in[0];
    const float* mask = (const float*)d_in[1];
    const float* Wq   = (const float*)d_in[2];
    const float* bq   = (const float*)d_in[3];
    const float* Wqa  = (const float*)d_in[4];
    const float* bqa  = (const float*)d_in[5];
    const float* Wk   = (const float*)d_in[6];
    const float* bk   = (const float*)d_in[7];
    const float* Wka  = (const float*)d_in[8];
    const float* bka  = (const float*)d_in[9];
    const float* Wt   = (const float*)d_in[10];
    const float* bt   = (const float*)d_in[11];
    float* out = (float*)d_out;

    float *sco, *part, *pq, *pk, *wtt;
    __half *Ah, *mqh, *mkh, *bqk, *bt4;
    cudaGetSymbolAddress((void**)&Ah,  g_Ah);
    cudaGetSymbolAddress((void**)&mqh, g_mqh);
    cudaGetSymbolAddress((void**)&mkh, g_mkh);
    cudaGetSymbolAddress((void**)&bqk, g_Bqk);
    cudaGetSymbolAddress((void**)&wtt, g_Wtt);
    cudaGetSymbolAddress((void**)&bt4, g_Bt4);
    cudaGetSymbolAddress((void**)&sco, g_score);
    cudaGetSymbolAddress((void**)&part, g_part);
    cudaGetSymbolAddress((void**)&pq, g_pq);
    cudaGetSymbolAddress((void**)&pk, g_pk);

    const int GSMEM = 122880;
    cudaFuncSetAttribute(hmma_gemm_kernel<false>,
                         cudaFuncAttributeMaxDynamicSharedMemorySize, GSMEM);
    cudaFuncSetAttribute(hmma_gemm_kernel<true>,
                         cudaFuncAttributeMaxDynamicSharedMemorySize, GSMEM);

    // ---- weight prep (1 launch) + hs convert
    wprep_all_kernel<<<dim3(32, 32, 3), dim3(32, 8)>>>(Wq, Wk, Wt, bqk, wtt);
    asplit_kernel<<<16384, 256>>>(hs, Ah);

    // ---- fused mixed_q / mixed_k GEMM (N=2048), fp16 outputs w/ bias
    hmma_gemm_kernel<false><<<dim3(8, 256), 256, GSMEM>>>(
        Ah, bqk, bq, bk, nullptr, mqh, mkh);

    // ---- q attention pooling
    score_kernel<<<1024, 1024, 32768>>>(mqh, Wqa, bqa, mask, nullptr, sco);
    pool_partial_kernel<<<dim3(64, 8), 256>>>(sco, mqh, part);
    pool_combine_kernel<<<64, 64>>>(part, nullptr, pq);

    // ---- k attention pooling (mixed_qk = mixed_k * pooled_q, never materialized)
    score_kernel<<<1024, 1024, 32768>>>(mkh, Wka, bka, mask, pq, sco);
    pool_partial_kernel<<<dim3(64, 8), 256>>>(sco, mkh, part);
    pool_combine_kernel<<<64, 64>>>(part, pq, pk);

    // ---- fold pooled_k into Wt: Bt4[b] = fp16(Wt^T * pk[b])
    wtscale_kernel<<<1024, 256>>>(wtt, pk, bt4);

    // ---- out = mixed_q @ Bt4[batch] + bt + mixed_q  (A column-scale folded into B)
    hmma_gemm_kernel<true><<<dim3(4, 256), 256, GSMEM>>>(
        mqh, bt4, bt, nullptr, mqh, out, nullptr);
}

// round 17
// speedup vs baseline: 1.5107x; 1.5107x over previous
#include <cuda_runtime.h>
#include <cuda_fp16.h>
#include <math.h>
#include <stdint.h>

#define B_  4
#define S_  8192
#define D_  1024
#define H_  16
#define M_  (B_*S_)

// ---------------- scratch (device globals; no cudaMalloc) ----------------
__device__ __half g_Ah[(size_t)M_ * D_];                // fp16(hs)
__device__ __half g_mqh[(size_t)M_ * D_];               // fp16 mixed_q
__device__ __half g_mkh[(size_t)M_ * D_];               // fp16 mixed_k
__device__ __half g_Bqk[2048 * 1024];                   // [n,k] fp16 (Wq cols | Wk cols)
__device__ float  g_Wtt[1024 * 1024];                   // Wt^T fp32 [n,k]
__device__ __half g_Bt4[4 * 1024 * 1024];               // per-batch fp16(Wt^T * pk)
__device__ float g_score[B_ * H_ * S_];
__device__ float g_part[512 * 65];
__device__ float g_pq[B_ * D_];
__device__ float g_pk[B_ * D_];

// ---------------- helpers (sm_80-era PTX only: portable to sm_103) ----------------
__device__ __forceinline__ uint32_t smem_u32(const void* p) {
    uint32_t a;
    asm("{ .reg .u64 t; cvta.to.shared.u64 t, %1; cvt.u32.u64 %0, t; }" : "=r"(a) : "l"(p));
    return a;
}
__device__ __forceinline__ void cp16(uint32_t dst, const void* src) {
    asm volatile("cp.async.cg.shared.global [%0], [%1], 16;" :: "r"(dst), "l"(src));
}
__device__ __forceinline__ void ldsm4(uint32_t* r, uint32_t addr) {
    asm volatile("ldmatrix.sync.aligned.m8n8.x4.shared.b16 {%0,%1,%2,%3}, [%4];"
                 : "=r"(r[0]), "=r"(r[1]), "=r"(r[2]), "=r"(r[3]) : "r"(addr));
}
__device__ __forceinline__ void mma16816(float* d, const uint32_t* a, const uint32_t* b) {
    asm volatile("mma.sync.aligned.m16n8k16.row.col.f32.f16.f16.f32 "
                 "{%0,%1,%2,%3}, {%4,%5,%6,%7}, {%8,%9}, {%0,%1,%2,%3};"
                 : "+f"(d[0]), "+f"(d[1]), "+f"(d[2]), "+f"(d[3])
                 : "r"(a[0]), "r"(a[1]), "r"(a[2]), "r"(a[3]), "r"(b[0]), "r"(b[1]));
}

// =====================================================================
// Weight prep, single launch: z=0 Wq->bqk, z=1 Wk->bqk+1M (fp16),
// z=2 Wt->wtt (fp32). All transpose [k][n] -> [n][k].
// =====================================================================
__global__ void wprep_all_kernel(const float* __restrict__ Wq, const float* __restrict__ Wk,
                                 const float* __restrict__ Wt,
                                 __half* __restrict__ bqk, float* __restrict__ wtt)
{
    __shared__ float t[32][33];
    const float* W = (blockIdx.z == 0) ? Wq : (blockIdx.z == 1) ? Wk : Wt;
    int n0 = blockIdx.x * 32, k0 = blockIdx.y * 32;
    int tx = threadIdx.x, ty = threadIdx.y;
    for (int i = ty; i < 32; i += 8)
        t[i][tx] = W[(size_t)(k0 + i) * 1024 + n0 + tx];
    __syncthreads();
    if (blockIdx.z < 2) {
        __half* o = bqk + (size_t)blockIdx.z * 1024 * 1024;
        for (int i = ty; i < 32; i += 8)
            o[(size_t)(n0 + i) * 1024 + k0 + tx] = __float2half(t[tx][i]);
    } else {
        for (int i = ty; i < 32; i += 8)
            wtt[(size_t)(n0 + i) * 1024 + k0 + tx] = t[tx][i];
    }
}

// B4[b][n][k] = fp16(Wtt[n][k] * pk[b][k])   (single rounding of the product)
__global__ __launch_bounds__(256)
void wtscale_kernel(const float* __restrict__ Wtt, const float* __restrict__ pk,
                    __half* __restrict__ B4)
{
    int i = blockIdx.x * 256 + threadIdx.x;   // float4 index into [n][k]
    int k4 = (i << 2) & 1023;
    float4 w = ((const float4*)Wtt)[i];
    #pragma unroll
    for (int b = 0; b < 4; b++) {
        float4 s = *(const float4*)&pk[b * 1024 + k4];
        __half2 h0 = __floats2half2_rn(w.x * s.x, w.y * s.y);
        __half2 h1 = __floats2half2_rn(w.z * s.z, w.w * s.w);
        ((uint2*)(B4 + ((size_t)b << 20)))[i] =
            make_uint2(*(uint32_t*)&h0, *(uint32_t*)&h1);
    }
}

// =====================================================================
// A convert: fp16 of hs (2 float4 per thread)
// =====================================================================
__global__ __launch_bounds__(256)
void asplit_kernel(const float* __restrict__ X, __half* __restrict__ hi)
{
    size_t i = ((size_t)blockIdx.x * 256 + threadIdx.x) * 2;   // float4 index
    #pragma unroll
    for (int j = 0; j < 2; j++) {
        float4 v = ((const float4*)X)[i + j];
        __half2 h0 = __floats2half2_rn(v.x, v.y);
        __half2 h1 = __floats2half2_rn(v.z, v.w);
        ((uint2*)hi)[i + j] = make_uint2(*(uint32_t*)&h0, *(uint32_t*)&h1);
    }
}

// =====================================================================
// HMMA fp16 1-pass GEMM. CTA 128x256, 8 warps, warp tile 64x64, BK=32,
// 4-stage cp.async.  G3=false: dual fp16 outputs (mq|mk) + fp32 bias.
// G3=true: per-batch B (Bt4), fp32 output, fp16 residual addC.
// =====================================================================
#define STAGE_BYTES 30720u
#define NSTAGE 4

__device__ __forceinline__ void issue_stage(
    int s, uint32_t smb, int brow, int bcol,
    const __half* Ab, const __half* Bb, int rr, int cc)
{
    const int st = s & (NSTAGE - 1);
    const int k0 = s << 5;
    uint32_t As = smb + (uint32_t)st * STAGE_BYTES;
    uint32_t Bs = As + 10240u;
    #pragma unroll
    for (int i = 0; i < 2; i++) {
        int r = rr + i * 64;
        cp16(As + (uint32_t)(r * 80 + cc * 2), Ab + (size_t)(brow + r) * 1024 + k0 + cc);
    }
    #pragma unroll
    for (int i = 0; i < 4; i++) {
        int r = rr + i * 64;
        cp16(Bs + (uint32_t)(r * 80 + cc * 2), Bb + (size_t)(bcol + r) * 1024 + k0 + cc);
    }
    asm volatile("cp.async.commit_group;" ::: "memory");
}

template<bool G3>
__global__ __launch_bounds__(256, 1)
void hmma_gemm_kernel(const __half* __restrict__ Ah, const __half* __restrict__ B,
                      const float* __restrict__ bias0, const float* __restrict__ bias1,
                      const __half* __restrict__ addCh,
                      void* __restrict__ C0v, void* __restrict__ C1v)
{
    extern __shared__ char smraw[];
    const uint32_t smb = smem_u32(smraw);
    const int tid = threadIdx.x, lane = tid & 31, wid = tid >> 5;
    const int wr = wid & 1, wc = wid >> 1;
    const int brow = blockIdx.y * 128, bcol = blockIdx.x * 256;

    const __half* Bb = B;
    if (G3) Bb += ((size_t)(brow >> 13)) << 20;   // per-batch scaled Wt

    float acc[4][8][4];
    #pragma unroll
    for (int mt = 0; mt < 4; mt++)
        #pragma unroll
        for (int nt = 0; nt < 8; nt++)
            #pragma unroll
            for (int j = 0; j < 4; j++) acc[mt][nt][j] = 0.f;

    const int rr = tid >> 2;
    const int cc = (tid & 3) * 8;

    issue_stage(0, smb, brow, bcol, Ah, Bb, rr, cc);
    issue_stage(1, smb, brow, bcol, Ah, Bb, rr, cc);
    issue_stage(2, smb, brow, bcol, Ah, Bb, rr, cc);

    const int am  = wr * 64 + (lane & 15);
    const int akh = (lane >> 4) * 8;
    const int g   = lane >> 3;
    const int bn  = wc * 64 + (lane & 7) + (g >> 1) * 8;
    const int bkh = (g & 1) * 8;

    for (int s = 0; s < 32; s++) {
        asm volatile("cp.async.wait_group 2;" ::: "memory");
        __syncthreads();
        if (s + 3 < 32) issue_stage(s + 3, smb, brow, bcol, Ah, Bb, rr, cc);
        else            asm volatile("cp.async.commit_group;" ::: "memory");

        uint32_t Asb = smb + (uint32_t)(s & (NSTAGE - 1)) * STAGE_BYTES;
        uint32_t Bsb = Asb + 10240u;
        #pragma unroll
        for (int kk = 0; kk < 2; kk++) {
            const int k = kk * 16;
            uint32_t a[4][4], b[4][4];
            #pragma unroll
            for (int mt = 0; mt < 4; mt++)
                ldsm4(a[mt], Asb + (uint32_t)((am + mt * 16) * 80 + (k + akh) * 2));
            #pragma unroll
            for (int bt = 0; bt < 4; bt++)
                ldsm4(b[bt], Bsb + (uint32_t)((bn + bt * 16) * 80 + (k + bkh) * 2));
            #pragma unroll
            for (int mt = 0; mt < 4; mt++)
                #pragma unroll
                for (int nt = 0; nt < 8; nt++)
                    mma16816(acc[mt][nt], a[mt], &b[nt >> 1][(nt & 1) * 2]);
        }
    }

    if (!G3) {
        // ---- fp16 dual-output epilogue (mixed_q | mixed_k), bias added
        const float* bias = bias0;
        __half* Cd = (__half*)C0v;
        int ceff = bcol;
        if (bcol >= 1024) { bias = bias1; Cd = (__half*)C1v; ceff = bcol - 1024; }
        #pragma unroll
        for (int mt = 0; mt < 4; mt++) {
            const int r = brow + wr * 64 + mt * 16 + (lane >> 2);
            #pragma unroll
            for (int nt = 0; nt < 8; nt++) {
                const int c = ceff + wc * 64 + nt * 8 + (lane & 3) * 2;
                float2 bi = *(const float2*)&bias[c];
                __half2 h0 = __floats2half2_rn(acc[mt][nt][0] + bi.x, acc[mt][nt][1] + bi.y);
                __half2 h1 = __floats2half2_rn(acc[mt][nt][2] + bi.x, acc[mt][nt][3] + bi.y);
                *(uint32_t*)&Cd[(size_t)r * 1024 + c] = *(uint32_t*)&h0;
                *(uint32_t*)&Cd[(size_t)(r + 8) * 1024 + c] = *(uint32_t*)&h1;
            }
        }
    } else {
        // ---- fp32 output epilogue with fp16 residual
        float* Cd = (float*)C0v;
        #pragma unroll
        for (int mt = 0; mt < 4; mt++) {
            const int r = brow + wr * 64 + mt * 16 + (lane >> 2);
            #pragma unroll
            for (int nt = 0; nt < 8; nt++) {
                const int c = bcol + wc * 64 + nt * 8 + (lane & 3) * 2;
                float2 bi = *(const float2*)&bias0[c];
                uint32_t a0u = *(const uint32_t*)&addCh[(size_t)r * 1024 + c];
                uint32_t a1u = *(const uint32_t*)&addCh[(size_t)(r + 8) * 1024 + c];
                float2 a0 = __half22float2(*(__half2*)&a0u);
                float2 a1 = __half22float2(*(__half2*)&a1u);
                float2 v0 = make_float2(acc[mt][nt][0] + bi.x + a0.x,
                                        acc[mt][nt][1] + bi.y + a0.y);
                float2 v1 = make_float2(acc[mt][nt][2] + bi.x + a1.x,
                                        acc[mt][nt][3] + bi.y + a1.y);
                *(float2*)&Cd[(size_t)r * 1024 + c] = v0;
                *(float2*)&Cd[(size_t)(r + 8) * 1024 + c] = v1;
            }
        }
    }
}

// =====================================================================
// score[b,h,s] = (X[b,s,:] (* mul[b,:]) . Wa[:,h] + ba[h]) * 0.125 + mask
// X fp16, Wa cached in smem as fp16, fp32 accumulation (R15-proven form).
// 1024 thr = 32 rows/block.
// =====================================================================
__global__ __launch_bounds__(1024)
void score_kernel(const __half* __restrict__ X, const float* __restrict__ Wa,
                  const float* __restrict__ ba, const float* __restrict__ mask,
                  const float* __restrict__ mul, float* __restrict__ score)
{
    extern __shared__ __half WaS[];  // [16][1024] transposed, fp16
    for (int idx = threadIdx.x; idx < 16 * 1024; idx += 1024) {
        int d = idx >> 4, h = idx & 15;
        WaS[h * 1024 + d] = __float2half(Wa[idx]);
    }
    __syncthreads();

    int warp = threadIdx.x >> 5, lane = threadIdx.x & 31;
    int m = blockIdx.x * 32 + warp;
    int b = m >> 13, s = m & 8191;
    const __half* xrow = X + (size_t)m * 1024;
    const float* mrow = mul ? (mul + b * 1024) : (const float*)0;

    float acc[16];
    #pragma unroll
    for (int h = 0; h < 16; h++) acc[h] = 0.f;

    #pragma unroll
    for (int it = 0; it < 8; it++) {
        int d = it * 128 + lane * 4;
        uint2 xu = *(const uint2*)&xrow[d];        // 4 halves
        float2 x01 = __half22float2(*(__half2*)&xu.x);
        float2 x23 = __half22float2(*(__half2*)&xu.y);
        if (mrow) {
            float4 mu = *(const float4*)&mrow[d];
            x01.x *= mu.x; x01.y *= mu.y; x23.x *= mu.z; x23.y *= mu.w;
        }
        #pragma unroll
        for (int h = 0; h < 16; h++) {
            uint2 wu = *(const uint2*)&WaS[h * 1024 + d];
            float2 w01 = __half22float2(*(__half2*)&wu.x);
            float2 w23 = __half22float2(*(__half2*)&wu.y);
            acc[h] += x01.x * w01.x + x01.y * w01.y + x23.x * w23.x + x23.y * w23.y;
        }
    }
    #pragma unroll
    for (int off = 16; off > 0; off >>= 1)
        #pragma unroll
        for (int h = 0; h < 16; h++)
            acc[h] += __shfl_xor_sync(0xffffffffu, acc[h], off);

    if (lane == 0) {
        float mk = mask[(b << 13) + s];
        #pragma unroll
        for (int h = 0; h < 16; h++)
            score[(size_t)(b * 16 + h) * 8192 + s] = (acc[h] + ba[h]) * 0.125f + mk;
    }
}

// =====================================================================
// Softmax pooling (no max subtraction: |score| < ~1, exp safe). X fp16.
// =====================================================================
__global__ __launch_bounds__(256)
void pool_partial_kernel(const float* __restrict__ score, const __half* __restrict__ X,
                         float* __restrict__ part)
{
    int bh = blockIdx.x, ch = blockIdx.y;
    int b = bh >> 4, h = bh & 15;
    const float* sc = score + ((size_t)bh << 13) + (ch << 10);
    int tid = threadIdx.x;
    float acc[64];
    #pragma unroll
    for (int j = 0; j < 64; j++) acc[j] = 0.f;
    float sumw = 0.f;
    for (int s = tid; s < 1024; s += 256) {
        float w = __expf(sc[s]);
        sumw += w;
        const uint4* xr = (const uint4*)(X + ((size_t)((b << 13) + (ch << 10) + s)) * 1024 + h * 64);
        #pragma unroll
        for (int j = 0; j < 8; j++) {
            uint4 u = xr[j];
            float2 f0 = __half22float2(*(__half2*)&u.x);
            float2 f1 = __half22float2(*(__half2*)&u.y);
            float2 f2 = __half22float2(*(__half2*)&u.z);
            float2 f3 = __half22float2(*(__half2*)&u.w);
            acc[8*j+0] += w*f0.x; acc[8*j+1] += w*f0.y;
            acc[8*j+2] += w*f1.x; acc[8*j+3] += w*f1.y;
            acc[8*j+4] += w*f2.x; acc[8*j+5] += w*f2.y;
            acc[8*j+6] += w*f3.x; acc[8*j+7] += w*f3.y;
        }
    }
    #pragma unroll
    for (int off = 16; off > 0; off >>= 1) {
        sumw += __shfl_xor_sync(0xffffffffu, sumw, off);
        #pragma unroll
        for (int j = 0; j < 64; j++)
            acc[j] += __shfl_xor_sync(0xffffffffu, acc[j], off);
    }
    __shared__ float sacc[8][64];
    __shared__ float ssum[8];
    int warp = tid >> 5, lane = tid & 31;
    if (lane == 0) ssum[warp] = sumw;
    #pragma unroll
    for (int j = 0; j < 64; j++)
        if ((j & 31) == lane) sacc[warp][j] = acc[j];
    __syncthreads();
    if (tid < 64) {
        float tot = 0.f, Z = 0.f;
        #pragma unroll
        for (int w = 0; w < 8; w++) { tot += sacc[w][tid]; Z += ssum[w]; }
        float* p = part + (size_t)(bh * 8 + ch) * 65;
        p[tid] = tot;
        if (tid == 0) p[64] = Z;
    }
}

__global__ void pool_combine_kernel(const float* __restrict__ part, const float* __restrict__ mul,
                                    float* __restrict__ pooled)
{
    int bh = blockIdx.x, tid = threadIdx.x;  // block 64
    int b = bh >> 4, h = bh & 15;
    float tot = 0.f, Z = 0.f;
    #pragma unroll
    for (int ch = 0; ch < 8; ch++) {
        const float* p = part + (size_t)(bh * 8 + ch) * 65;
        tot += p[tid]; Z += p[64];
    }
    float r = tot / Z;
    if (mul) r *= mul[b * 1024 + h * 64 + tid];
    pooled[b * 1024 + h * 64 + tid] = r;
}

// =====================================================================
extern "C" void kernel_launch(void* const* d_in, const int* in_sizes, int n_in,
                              void* d_out, int out_size)
{
    const float* hs   = (const float*)d_in[0];
    const float* mask = (const float*)d_in[1];
    const float* Wq   = (const float*)d_in[2];
    const float* bq   = (const float*)d_in[3];
    const float* Wqa  = (const float*)d_in[4];
    const float* bqa  = (const float*)d_in[5];
    const float* Wk   = (const float*)d_in[6];
    const float* bk   = (const float*)d_in[7];
    const float* Wka  = (const float*)d_in[8];
    const float* bka  = (const float*)d_in[9];
    const float* Wt   = (const float*)d_in[10];
    const float* bt   = (const float*)d_in[11];
    float* out = (float*)d_out;

    float *sco, *part, *pq, *pk, *wtt;
    __half *Ah, *mqh, *mkh, *bqk, *bt4;
    cudaGetSymbolAddress((void**)&Ah,  g_Ah);
    cudaGetSymbolAddress((void**)&mqh, g_mqh);
    cudaGetSymbolAddress((void**)&mkh, g_mkh);
    cudaGetSymbolAddress((void**)&bqk, g_Bqk);
    cudaGetSymbolAddress((void**)&wtt, g_Wtt);
    cudaGetSymbolAddress((void**)&bt4, g_Bt4);
    cudaGetSymbolAddress((void**)&sco, g_score);
    cudaGetSymbolAddress((void**)&part, g_part);
    cudaGetSymbolAddress((void**)&pq, g_pq);
    cudaGetSymbolAddress((void**)&pk, g_pk);

    const int GSMEM = 122880;
    cudaFuncSetAttribute(hmma_gemm_kernel<false>,
                         cudaFuncAttributeMaxDynamicSharedMemorySize, GSMEM);
    cudaFuncSetAttribute(hmma_gemm_kernel<true>,
                         cudaFuncAttributeMaxDynamicSharedMemorySize, GSMEM);

    // ---- weight prep (1 launch) + hs convert
    wprep_all_kernel<<<dim3(32, 32, 3), dim3(32, 8)>>>(Wq, Wk, Wt, bqk, wtt);
    asplit_kernel<<<16384, 256>>>(hs, Ah);

    // ---- fused mixed_q / mixed_k GEMM (N=2048), fp16 outputs w/ bias
    hmma_gemm_kernel<false><<<dim3(8, 256), 256, GSMEM>>>(
        Ah, bqk, bq, bk, nullptr, mqh, mkh);

    // ---- q attention pooling
    score_kernel<<<1024, 1024, 32768>>>(mqh, Wqa, bqa, mask, nullptr, sco);
    pool_partial_kernel<<<dim3(64, 8), 256>>>(sco, mqh, part);
    pool_combine_kernel<<<64, 64>>>(part, nullptr, pq);

    // ---- k attention pooling (mixed_qk = mixed_k * pooled_q, never materialized)
    score_kernel<<<1024, 1024, 32768>>>(mkh, Wka, bka, mask, pq, sco);
    pool_partial_kernel<<<dim3(64, 8), 256>>>(sco, mkh, part);
    pool_combine_kernel<<<64, 64>>>(part, pq, pk);

    // ---- fold pooled_k into Wt: Bt4[b] = fp16(Wt^T * pk[b])
    wtscale_kernel<<<1024, 256>>>(wtt, pk, bt4);

    // ---- out = mixed_q @ Bt4[batch] + bt + mixed_q  (A column-scale folded into B)
    hmma_gemm_kernel<true><<<dim3(4, 256), 256, GSMEM>>>(
        mqh, bt4, bt, nullptr, mqh, out, nullptr);
}